// round 5
// baseline (speedup 1.0000x reference)
#include <cuda_runtime.h>

static constexpr int NN   = 25000;
static constexpr int NE   = 500000;
static constexpr int CH   = 128;
static constexpr int OUTW = 2048;
static constexpr int NPB  = 4;      // nodes per fused block

// ---------------- scratch (static device globals; no allocation allowed) ----
__device__ float g_h[NN * CH];                 // 12.8 MB
__device__ float g_x3[(size_t)NE * 64];        // 128 MB
__device__ float g_agg[(size_t)NN * 2048];     // 204.8 MB
__device__ float g_W4p[32768];                 // packed W4 (128 KB)
__device__ int   g_cnt[NN];                    // zero-init; scan re-zeroes
__device__ int   g_off[NN + 1];
__device__ int   g_cur[NN];
__device__ int   g_sorted[NE];
__device__ int   g_send[NE];
__device__ int   g_recv[NE];

__device__ __forceinline__ float silu(float x) {
    return __fdividef(x, 1.0f + __expf(-x));
}

// packed f32x2 helpers (Blackwell; PTX-only)
__device__ __forceinline__ unsigned long long bcast2(float a) {
    unsigned long long r;
    asm("mov.b64 %0, {%1, %1};" : "=l"(r) : "f"(a));
    return r;
}
__device__ __forceinline__ void fma2(unsigned long long& acc, unsigned long long a,
                                     unsigned long long b) {
    asm("fma.rn.f32x2 %0, %1, %2, %0;" : "+l"(acc) : "l"(a), "l"(b));
}
__device__ __forceinline__ unsigned long long mul2(unsigned long long a,
                                                   unsigned long long b) {
    unsigned long long r;
    asm("mul.rn.f32x2 %0, %1, %2;" : "=l"(r) : "l"(a), "l"(b));
    return r;
}
__device__ __forceinline__ float2 unpack2(unsigned long long v) {
    float lo, hi;
    asm("mov.b64 {%0, %1}, %2;" : "=f"(lo), "=f"(hi) : "l"(v));
    return make_float2(lo, hi);
}

// ---------------- convert (+ fused receiver histogram) ----------------------
// JAX with x64 disabled downcasts int64 edge_index to int32; detect layout.
__global__ void k_convert(const int* __restrict__ ei) {
    int e = blockIdx.x * 256 + threadIdx.x;
    if (e >= NE) return;
    bool is64 = true;
#pragma unroll
    for (int i = 0; i < 8; i++) is64 &= (__ldg(&ei[2 * i + 1]) == 0);
    int s, r;
    if (is64) {
        const long long* p = (const long long*)ei;
        s = (int)p[e];
        r = (int)p[NE + e];
    } else {
        s = ei[e];
        r = ei[NE + e];
    }
    s = min(max(s, 0), NN - 1);
    r = min(max(r, 0), NN - 1);
    g_send[e] = s;
    g_recv[e] = r;
    atomicAdd(&g_cnt[r], 1);
}

// ---------------- scan (exclusive prefix over g_cnt; re-zeroes g_cnt) --------
__global__ void k_scan() {
    __shared__ int s[1024];
    const int t = threadIdx.x;
    const int CK = 25;  // 1024*25 >= NN
    const int base = t * CK;
    int loc[CK];
    int sum = 0;
#pragma unroll
    for (int i = 0; i < CK; i++) {
        int idx = base + i;
        int c = (idx < NN) ? g_cnt[idx] : 0;
        if (idx < NN) g_cnt[idx] = 0;  // reset for next graph replay
        loc[i] = sum;
        sum += c;
    }
    s[t] = sum;
    __syncthreads();
    for (int d = 1; d < 1024; d <<= 1) {
        int v = (t >= d) ? s[t - d] : 0;
        __syncthreads();
        s[t] += v;
        __syncthreads();
    }
    int pre = (t == 0) ? 0 : s[t - 1];
#pragma unroll
    for (int i = 0; i < CK; i++) {
        int idx = base + i;
        if (idx < NN) {
            int o = pre + loc[i];
            g_off[idx] = o;
            g_cur[idx] = o;
        }
    }
    if (t == 1023) g_off[NN] = s[1023];
}
__global__ void k_scatter() {
    int e = blockIdx.x * 256 + threadIdx.x;
    if (e < NE) {
        int pos = atomicAdd(&g_cur[g_recv[e]], 1);
        g_sorted[pos] = e;
    }
}

// ---------------- k_pre: r123 (f32x2) + h GEMM + W4 packing, one launch ------
static constexpr int R123_BLKS = (NE + 63) / 64;   // 7813
static constexpr int H_BLKS    = (NN + 7) / 8;     // 3125
static constexpr int W4P_BLKS  = 64;               // 8192 float4 / 128 thr

__global__ void __launch_bounds__(128) k_pre(
    const float* __restrict__ ef, const float* __restrict__ W1,
    const float* __restrict__ W2, const float* __restrict__ W3,
    const float* __restrict__ nf, const float* __restrict__ Wup,
    const float* __restrict__ W4) {
    __shared__ float efs[64 * 8];
    __shared__ float bufA[64 * 64];
    __shared__ float bufB[64 * 64];
    __shared__ float fs[8 * CH];
    const int t = threadIdx.x;

    if (blockIdx.x < R123_BLKS) {
        // ---- radial layers 1-3 fused ----
        const int e0 = blockIdx.x * 64;
        for (int i = t; i < 64 * 8; i += 128) {
            int e = e0 + i / 8;
            efs[i] = (e < NE) ? ef[(size_t)e * 8 + (i & 7)] : 0.0f;
        }
        __syncthreads();
        const int tr = t >> 4;
        const int tc = t & 15;
        {
            unsigned long long acc[8][2];
#pragma unroll
            for (int i = 0; i < 8; i++) { acc[i][0] = 0ULL; acc[i][1] = 0ULL; }
#pragma unroll
            for (int k = 0; k < 8; k++) {
                ulonglong2 w = __ldg((const ulonglong2*)&W1[k * 64 + tc * 4]);
#pragma unroll
                for (int i = 0; i < 8; i++) {
                    unsigned long long a2 = bcast2(efs[(tr * 8 + i) * 8 + k]);
                    fma2(acc[i][0], a2, w.x);
                    fma2(acc[i][1], a2, w.y);
                }
            }
#pragma unroll
            for (int i = 0; i < 8; i++) {
                float2 p0 = unpack2(acc[i][0]), p1 = unpack2(acc[i][1]);
                float* d = &bufA[(tr * 8 + i) * 64 + tc * 4];
                d[0] = silu(p0.x); d[1] = silu(p0.y);
                d[2] = silu(p1.x); d[3] = silu(p1.y);
            }
        }
        __syncthreads();
        {
            unsigned long long acc[8][2];
#pragma unroll
            for (int i = 0; i < 8; i++) { acc[i][0] = 0ULL; acc[i][1] = 0ULL; }
            for (int k = 0; k < 64; k++) {
                ulonglong2 w = __ldg((const ulonglong2*)&W2[k * 64 + tc * 4]);
#pragma unroll
                for (int i = 0; i < 8; i++) {
                    unsigned long long a2 = bcast2(bufA[(tr * 8 + i) * 64 + k]);
                    fma2(acc[i][0], a2, w.x);
                    fma2(acc[i][1], a2, w.y);
                }
            }
            __syncthreads();
#pragma unroll
            for (int i = 0; i < 8; i++) {
                float2 p0 = unpack2(acc[i][0]), p1 = unpack2(acc[i][1]);
                float* d = &bufB[(tr * 8 + i) * 64 + tc * 4];
                d[0] = silu(p0.x); d[1] = silu(p0.y);
                d[2] = silu(p1.x); d[3] = silu(p1.y);
            }
        }
        __syncthreads();
        {
            unsigned long long acc[8][2];
#pragma unroll
            for (int i = 0; i < 8; i++) { acc[i][0] = 0ULL; acc[i][1] = 0ULL; }
            for (int k = 0; k < 64; k++) {
                ulonglong2 w = __ldg((const ulonglong2*)&W3[k * 64 + tc * 4]);
#pragma unroll
                for (int i = 0; i < 8; i++) {
                    unsigned long long a2 = bcast2(bufB[(tr * 8 + i) * 64 + k]);
                    fma2(acc[i][0], a2, w.x);
                    fma2(acc[i][1], a2, w.y);
                }
            }
#pragma unroll
            for (int i = 0; i < 8; i++) {
                int e = e0 + tr * 8 + i;
                if (e < NE) {
                    float2 p0 = unpack2(acc[i][0]), p1 = unpack2(acc[i][1]);
                    float4 v = make_float4(silu(p0.x), silu(p0.y), silu(p1.x), silu(p1.y));
                    *(float4*)&g_x3[(size_t)e * 64 + tc * 4] = v;
                }
            }
        }
    } else if (blockIdx.x < R123_BLKS + H_BLKS) {
        // ---- h = node_feats @ W_up ----
        const int n0 = (blockIdx.x - R123_BLKS) * 8;
        for (int i = t; i < 8 * CH; i += 128) {
            int n = n0 + i / CH;
            fs[i] = (n < NN) ? nf[(size_t)n * CH + (i & (CH - 1))] : 0.0f;
        }
        __syncthreads();
        float acc[8];
#pragma unroll
        for (int i = 0; i < 8; i++) acc[i] = 0.0f;
        for (int k = 0; k < CH; k++) {
            float wv = __ldg(&Wup[k * CH + t]);
#pragma unroll
            for (int i = 0; i < 8; i++) acc[i] += fs[i * CH + k] * wv;
        }
#pragma unroll
        for (int i = 0; i < 8; i++) {
            int n = n0 + i;
            if (n < NN) g_h[(size_t)n * CH + t] = acc[i];
        }
    } else {
        // ---- W4 packing: g_W4p[k2*256 + tt] = float4(W4[2k2][c0], W4[2k2][c1],
        //                                             W4[2k2+1][c0], W4[2k2+1][c1])
        int idx = (blockIdx.x - R123_BLKS - H_BLKS) * 128 + t;  // 0..8191
        if (idx < 8192) {
            int k2 = idx >> 8;
            int tt = idx & 255;
            int c0 = 2 * tt;
            float4 v = make_float4(__ldg(&W4[(size_t)(2 * k2) * 512 + c0]),
                                   __ldg(&W4[(size_t)(2 * k2) * 512 + c0 + 1]),
                                   __ldg(&W4[(size_t)(2 * k2 + 1) * 512 + c0]),
                                   __ldg(&W4[(size_t)(2 * k2 + 1) * 512 + c0 + 1]));
            *(float4*)&g_W4p[idx * 4] = v;
        }
    }
}

// ---------------- fused r4 + gather + weight + segment-sum -------------------
// Per block: 4 nodes. W4p in smem (128KB). Per node, edges chunked x8:
//   acc[e] (f32x2, thread cols 2t,2t+1) = x3[e,:] @ W4
//   hr = acc * h[send[e]]; agg[m] += hr * sh[e][m];  store agg/20 -> g_agg.
// smem float layout: [0,32768) W4p | 32768+buf*1024 x3 dup | 34816+buf*128 sh |
//                    int at 35072+buf*8 send ids.  Total 35088 floats = 140352 B.
static constexpr int FUSED_SMEM = 35088 * 4;
static constexpr int X3D_F = 32768;
static constexpr int SHS_F = 34816;
static constexpr int SND_I = 35072;

__device__ __forceinline__ bool next_chunk(const int* offr, int& ln, int& ec) {
    ec += 8;
    for (;;) {
        if (ln >= NPB) return false;
        if (ec < offr[ln + 1] - offr[ln]) return true;
        ln++;
        ec = 0;
    }
}

__global__ void __launch_bounds__(256) k_fused(const float* __restrict__ ea) {
    extern __shared__ float sm[];
    int* snd = ((int*)sm) + SND_I;
    const int t  = threadIdx.x;
    const int n0 = blockIdx.x * NPB;

    // stage packed W4 (128 KB)
    {
        const float4* src = (const float4*)g_W4p;
        float4* dst = (float4*)sm;
        for (int i = t; i < 8192; i += 256) dst[i] = src[i];
    }
    int offr[NPB + 1];
#pragma unroll
    for (int i = 0; i <= NPB; i++) offr[i] = g_off[n0 + i];

    const int eX  = t >> 5;          // edge slot for x3 prefetch (0..7)
    const int kX  = (t & 31) * 2;    // k pair
    const int cl2 = 2 * (t & 63);    // local col pair within 128
    const int l   = t >> 6;          // path 0..3
    const int offl = (l == 0) ? 0 : (l == 1) ? 1 : (l == 2) ? 4 : 9;
    const int ml   = 2 * l + 1;

    // prefetch registers
    float2 px = make_float2(0.f, 0.f);
    float  psh = 0.f;
    int    psend = 0;

    // prologue: prefetch first chunk
    {
        int pln = 0, pec = -8;
        if (next_chunk(offr, pln, pec)) {
            int i0  = offr[pln] + pec;
            int cnt = min(8, offr[pln + 1] - i0);
            if (eX < cnt) {
                int eid = g_sorted[i0 + eX];
                px = *(const float2*)&g_x3[(size_t)eid * 64 + kX];
            }
            if (t < 128) {
                int eS = t >> 4;
                if (eS < cnt) {
                    int eid = g_sorted[i0 + eS];
                    psh = __ldg(&ea[(size_t)eid * 16 + (t & 15)]);
                }
            }
            if (t < 8 && t < cnt) psend = g_send[g_sorted[i0 + t]];
        }
    }

    int buf = 0;
    for (int ln = 0; ln < NPB; ln++) {
        const int n   = n0 + ln;
        const int deg = offr[ln + 1] - offr[ln];
        unsigned long long agg[7];
#pragma unroll
        for (int j = 0; j < 7; j++) agg[j] = 0ULL;

        for (int ec = 0; ec < deg; ec += 8) {
            // ---- commit prefetched chunk to smem ----
            __syncthreads();
            {
                float4 d = make_float4(px.x, px.x, px.y, px.y);
                *(float4*)&sm[X3D_F + buf * 1024 + eX * 128 + (t & 31) * 4] = d;
                if (t < 128) sm[SHS_F + buf * 128 + t] = psh;
                if (t < 8) snd[buf * 8 + t] = psend;
            }
            __syncthreads();

            // ---- issue h loads (consumed after k-loop) ----
            unsigned long long h2[8];
#pragma unroll
            for (int e = 0; e < 8; e++)
                h2[e] = *(const unsigned long long*)
                            &g_h[(size_t)snd[buf * 8 + e] * 128 + cl2];

            // ---- prefetch next chunk ----
            px = make_float2(0.f, 0.f);
            psh = 0.f;
            psend = 0;
            {
                int nln = ln, nec = ec;
                if (next_chunk(offr, nln, nec)) {
                    int i0  = offr[nln] + nec;
                    int cnt = min(8, offr[nln + 1] - i0);
                    if (eX < cnt) {
                        int eid = g_sorted[i0 + eX];
                        px = *(const float2*)&g_x3[(size_t)eid * 64 + kX];
                    }
                    if (t < 128) {
                        int eS = t >> 4;
                        if (eS < cnt) {
                            int eid = g_sorted[i0 + eS];
                            psh = __ldg(&ea[(size_t)eid * 16 + (t & 15)]);
                        }
                    }
                    if (t < 8 && t < cnt) psend = g_send[g_sorted[i0 + t]];
                }
            }

            // ---- k-loop: acc[e] = x3[e,:] @ W4[:, 2t:2t+1] (f32x2) ----
            unsigned long long acc[8];
#pragma unroll
            for (int e = 0; e < 8; e++) acc[e] = 0ULL;
            const ulonglong2* Wv = (const ulonglong2*)sm;
            const ulonglong2* Xv = (const ulonglong2*)&sm[X3D_F + buf * 1024];
#pragma unroll 4
            for (int k2 = 0; k2 < 32; k2++) {
                ulonglong2 w = Wv[k2 * 256 + t];
#pragma unroll
                for (int e = 0; e < 8; e++) {
                    ulonglong2 x = Xv[e * 32 + k2];
                    fma2(acc[e], x.x, w.x);
                    fma2(acc[e], x.y, w.y);
                }
            }

            // ---- epilogue: agg[m] += (acc*h) * sh  (padding edges are zero) --
            const float* shp = &sm[SHS_F + buf * 128];
#pragma unroll
            for (int e = 0; e < 8; e++) {
                unsigned long long hr = mul2(acc[e], h2[e]);
#pragma unroll
                for (int j = 0; j < 7; j++)
                    if (j < ml) fma2(agg[j], hr, bcast2(shp[e * 16 + offl + j]));
            }
            buf ^= 1;
        }

        // ---- store agg / 20 ----
        const float inv = 0.05f;
#pragma unroll
        for (int j = 0; j < 7; j++)
            if (j < ml) {
                float2 v = unpack2(agg[j]);
                *(float2*)&g_agg[(size_t)n * 2048 + (offl + j) * 128 + cl2] =
                    make_float2(v.x * inv, v.y * inv);
            }
    }
}

// ---------------- out transform per path (f32x2) -----------------------------
template <int ML, int NB, int OFFM, int COLOFF>
__global__ void __launch_bounds__(256) k_out(const float* __restrict__ Wl,
                                             float* __restrict__ out) {
    constexpr int NR = ML * NB;
    __shared__ float As[64 * 128];
    const int t  = threadIdx.x;
    const int n0 = blockIdx.x * NB;
    for (int i = t; i < 64 * 128; i += 256) {
        int r = i >> 7, c = i & 127;
        float v = 0.0f;
        if (r < NR) {
            int n = n0 + r / ML;
            if (n < NN) v = g_agg[(size_t)n * 2048 + (OFFM + r % ML) * 128 + c];
        }
        As[i] = v;
    }
    __syncthreads();
    const int rg = t >> 5, lane = t & 31;
    unsigned long long acc[8][2];
#pragma unroll
    for (int i = 0; i < 8; i++) { acc[i][0] = 0ULL; acc[i][1] = 0ULL; }
    for (int c = 0; c < 128; c++) {
        ulonglong2 w = __ldg((const ulonglong2*)&Wl[c * 128 + lane * 4]);
#pragma unroll
        for (int i = 0; i < 8; i++) {
            unsigned long long a2 = bcast2(As[(rg * 8 + i) * 128 + c]);
            fma2(acc[i][0], a2, w.x);
            fma2(acc[i][1], a2, w.y);
        }
    }
#pragma unroll
    for (int i = 0; i < 8; i++) {
        int r = rg * 8 + i;
        if (r < NR) {
            int n = n0 + r / ML;
            if (n < NN) {
                int m = r % ML;
                float* op = out + (size_t)n * OUTW + COLOFF + m;
                float2 p0 = unpack2(acc[i][0]), p1 = unpack2(acc[i][1]);
                float v[4] = {p0.x, p0.y, p1.x, p1.y};
#pragma unroll
                for (int j = 0; j < 4; j++) {
                    int d = lane * 4 + j;
                    op[(size_t)d * ML] = v[j];
                }
            }
        }
    }
}

// ---------------- one-body term ----------------------------------------------
__global__ void k_ob(const float* __restrict__ pf, const float* __restrict__ nf,
                     const float* __restrict__ lc, const float* __restrict__ Wp,
                     const float* __restrict__ Wn, const float* __restrict__ Wc,
                     float* __restrict__ out) {
    __shared__ float pfs[16 * 16];
    __shared__ float nfs[16 * 128];
    __shared__ float lcs[16];
    const int t  = threadIdx.x;
    const int n0 = blockIdx.x * 16;
    for (int i = t; i < 16 * 16; i += 128) {
        int n = n0 + i / 16;
        pfs[i] = (n < NN) ? pf[(size_t)n * 16 + (i & 15)] * 0.1f : 0.0f;
    }
    for (int i = t; i < 16 * 128; i += 128) {
        int n = n0 + i / 128;
        nfs[i] = (n < NN) ? nf[(size_t)n * 128 + (i & 127)] : 0.0f;
    }
    if (t < 16) {
        int n = n0 + t;
        lcs[t] = (n < NN) ? lc[n] : 0.0f;
    }
    __syncthreads();
    float acc[16];
    float wc = __ldg(&Wc[t]);
#pragma unroll
    for (int i = 0; i < 16; i++) acc[i] = lcs[i] * wc;
    for (int k = 0; k < 16; k++) {
        float wv = __ldg(&Wp[k * 128 + t]);
#pragma unroll
        for (int i = 0; i < 16; i++) acc[i] += pfs[i * 16 + k] * wv;
    }
    for (int k = 0; k < 128; k++) {
        float wv = __ldg(&Wn[k * 128 + t]);
#pragma unroll
        for (int i = 0; i < 16; i++) acc[i] += nfs[i * 128 + k] * wv;
    }
#pragma unroll
    for (int i = 0; i < 16; i++) {
        int n = n0 + i;
        if (n < NN) out[(size_t)n * OUTW + t] += acc[i];
    }
}

// ---------------- launch -----------------------------------------------------
extern "C" void kernel_launch(void* const* d_in, const int* in_sizes, int n_in,
                              void* d_out, int out_size) {
    const float* node_feats = (const float*)d_in[1];
    const float* edge_attrs = (const float*)d_in[2];
    const float* edge_feats = (const float*)d_in[3];
    const int*   edge_index = (const int*)d_in[4];
    const float* potential  = (const float*)d_in[5];
    const float* charges    = (const float*)d_in[6];
    const float* W_up = (const float*)d_in[7];
    const float* W1   = (const float*)d_in[8];
    const float* W2   = (const float*)d_in[9];
    const float* W3   = (const float*)d_in[10];
    const float* W4   = (const float*)d_in[11];
    const float* Wout = (const float*)d_in[12];
    const float* Wp   = (const float*)d_in[13];
    const float* Wn   = (const float*)d_in[14];
    const float* Wc   = (const float*)d_in[15];
    float*       out  = (float*)d_out;

    cudaFuncSetAttribute(k_fused, cudaFuncAttributeMaxDynamicSharedMemorySize,
                         FUSED_SMEM);

    k_convert<<<(NE + 255) / 256, 256>>>(edge_index);                 // 0
    k_scan<<<1, 1024>>>();                                            // 1
    k_scatter<<<(NE + 255) / 256, 256>>>();                           // 2
    k_pre<<<R123_BLKS + H_BLKS + W4P_BLKS, 128>>>(                    // 3 <- profiled
        edge_feats, W1, W2, W3, node_feats, W_up, W4);
    k_fused<<<NN / NPB, 256, FUSED_SMEM>>>(edge_attrs);               // 4

    // per-path out transform
    k_out<1, 64, 0, 0><<<(NN + 63) / 64, 256>>>(Wout, out);
    k_out<3, 21, 1, 128><<<(NN + 20) / 21, 256>>>(Wout + 1 * CH * CH, out);
    k_out<5, 12, 4, 512><<<(NN + 11) / 12, 256>>>(Wout + 2 * CH * CH, out);
    k_out<7, 9, 9, 1152><<<(NN + 8) / 9, 256>>>(Wout + 3 * CH * CH, out);

    // one-body correction into cols [0,128)
    k_ob<<<(NN + 15) / 16, 128>>>(potential, node_feats, charges, Wp, Wn, Wc, out);
}

// round 6
// speedup vs baseline: 1.3629x; 1.3629x over previous
#include <cuda_runtime.h>

static constexpr int NN   = 25000;
static constexpr int NE   = 500000;
static constexpr int CH   = 128;
static constexpr int OUTW = 2048;

// ---------------- scratch (static device globals; no allocation allowed) ----
__device__ float g_h[NN * CH];                   // 12.8 MB
__device__ float g_x3[(size_t)NE * 64];          // 128 MB
__device__ float g_w[(size_t)NE * 512];          // 1.024 GB (rank-ordered rows)
__device__ float g_sh[(size_t)NE * 16];          // 32 MB  (rank-ordered edge_attrs)
__device__ float g_agg[(size_t)NN * 2048];       // 204.8 MB
__device__ int   g_cnt[NN];                      // zero-init; scan re-zeroes
__device__ int   g_off[NN + 1];
__device__ int   g_ord[NE];                      // per-receiver ordinal
__device__ int   g_send[NE];
__device__ int   g_recv[NE];

__device__ __forceinline__ float silu(float x) {
    return __fdividef(x, 1.0f + __expf(-x));
}

// packed f32x2 helpers (Blackwell; PTX-only)
__device__ __forceinline__ unsigned long long bcast2(float a) {
    unsigned long long r;
    asm("mov.b64 %0, {%1, %1};" : "=l"(r) : "f"(a));
    return r;
}
__device__ __forceinline__ void fma2(unsigned long long& acc, unsigned long long a,
                                     unsigned long long b) {
    asm("fma.rn.f32x2 %0, %1, %2, %0;" : "+l"(acc) : "l"(a), "l"(b));
}
__device__ __forceinline__ float2 unpack2(unsigned long long v) {
    float lo, hi;
    asm("mov.b64 {%0, %1}, %2;" : "=f"(lo), "=f"(hi) : "l"(v));
    return make_float2(lo, hi);
}

// ---------------- convert: dtype detect + int32 + fused hist/ordinal ---------
__global__ void k_convert(const int* __restrict__ ei) {
    int e = blockIdx.x * 256 + threadIdx.x;
    if (e >= NE) return;
    bool is64 = true;
#pragma unroll
    for (int i = 0; i < 8; i++) is64 &= (__ldg(&ei[2 * i + 1]) == 0);
    int s, r;
    if (is64) {
        const long long* p = (const long long*)ei;
        s = (int)p[e];
        r = (int)p[NE + e];
    } else {
        s = ei[e];
        r = ei[NE + e];
    }
    s = min(max(s, 0), NN - 1);
    r = min(max(r, 0), NN - 1);
    g_send[e] = s;
    g_recv[e] = r;
    g_ord[e] = atomicAdd(&g_cnt[r], 1);   // ordinal within receiver + histogram
}

// ---------------- scan (exclusive prefix over g_cnt; re-zeroes g_cnt) --------
__global__ void k_scan() {
    __shared__ int s[1024];
    const int t = threadIdx.x;
    const int CK = 25;  // 1024*25 >= NN
    const int base = t * CK;
    int loc[CK];
    int sum = 0;
#pragma unroll
    for (int i = 0; i < CK; i++) {
        int idx = base + i;
        int c = (idx < NN) ? g_cnt[idx] : 0;
        if (idx < NN) g_cnt[idx] = 0;  // reset for next graph replay
        loc[i] = sum;
        sum += c;
    }
    s[t] = sum;
    __syncthreads();
    for (int d = 1; d < 1024; d <<= 1) {
        int v = (t >= d) ? s[t - d] : 0;
        __syncthreads();
        s[t] += v;
        __syncthreads();
    }
    int pre = (t == 0) ? 0 : s[t - 1];
#pragma unroll
    for (int i = 0; i < CK; i++) {
        int idx = base + i;
        if (idx < NN) g_off[idx] = pre + loc[i];
    }
    if (t == 1023) g_off[NN] = s[1023];
}

// ---------------- k_pre: r123 (f32x2) + h GEMM, one launch -------------------
static constexpr int R123_BLKS = (NE + 63) / 64;   // 7813
static constexpr int H_BLKS    = (NN + 7) / 8;     // 3125

__global__ void __launch_bounds__(128) k_pre(
    const float* __restrict__ ef, const float* __restrict__ W1,
    const float* __restrict__ W2, const float* __restrict__ W3,
    const float* __restrict__ nf, const float* __restrict__ Wup) {
    __shared__ float efs[64 * 8];
    __shared__ float bufA[64 * 64];
    __shared__ float bufB[64 * 64];
    __shared__ float fs[8 * CH];
    const int t = threadIdx.x;

    if (blockIdx.x < R123_BLKS) {
        const int e0 = blockIdx.x * 64;
        for (int i = t; i < 64 * 8; i += 128) {
            int e = e0 + i / 8;
            efs[i] = (e < NE) ? ef[(size_t)e * 8 + (i & 7)] : 0.0f;
        }
        __syncthreads();
        const int tr = t >> 4;
        const int tc = t & 15;
        {
            unsigned long long acc[8][2];
#pragma unroll
            for (int i = 0; i < 8; i++) { acc[i][0] = 0ULL; acc[i][1] = 0ULL; }
#pragma unroll
            for (int k = 0; k < 8; k++) {
                ulonglong2 w = __ldg((const ulonglong2*)&W1[k * 64 + tc * 4]);
#pragma unroll
                for (int i = 0; i < 8; i++) {
                    unsigned long long a2 = bcast2(efs[(tr * 8 + i) * 8 + k]);
                    fma2(acc[i][0], a2, w.x);
                    fma2(acc[i][1], a2, w.y);
                }
            }
#pragma unroll
            for (int i = 0; i < 8; i++) {
                float2 p0 = unpack2(acc[i][0]), p1 = unpack2(acc[i][1]);
                float* d = &bufA[(tr * 8 + i) * 64 + tc * 4];
                d[0] = silu(p0.x); d[1] = silu(p0.y);
                d[2] = silu(p1.x); d[3] = silu(p1.y);
            }
        }
        __syncthreads();
        {
            unsigned long long acc[8][2];
#pragma unroll
            for (int i = 0; i < 8; i++) { acc[i][0] = 0ULL; acc[i][1] = 0ULL; }
            for (int k = 0; k < 64; k++) {
                ulonglong2 w = __ldg((const ulonglong2*)&W2[k * 64 + tc * 4]);
#pragma unroll
                for (int i = 0; i < 8; i++) {
                    unsigned long long a2 = bcast2(bufA[(tr * 8 + i) * 64 + k]);
                    fma2(acc[i][0], a2, w.x);
                    fma2(acc[i][1], a2, w.y);
                }
            }
            __syncthreads();
#pragma unroll
            for (int i = 0; i < 8; i++) {
                float2 p0 = unpack2(acc[i][0]), p1 = unpack2(acc[i][1]);
                float* d = &bufB[(tr * 8 + i) * 64 + tc * 4];
                d[0] = silu(p0.x); d[1] = silu(p0.y);
                d[2] = silu(p1.x); d[3] = silu(p1.y);
            }
        }
        __syncthreads();
        {
            unsigned long long acc[8][2];
#pragma unroll
            for (int i = 0; i < 8; i++) { acc[i][0] = 0ULL; acc[i][1] = 0ULL; }
            for (int k = 0; k < 64; k++) {
                ulonglong2 w = __ldg((const ulonglong2*)&W3[k * 64 + tc * 4]);
#pragma unroll
                for (int i = 0; i < 8; i++) {
                    unsigned long long a2 = bcast2(bufB[(tr * 8 + i) * 64 + k]);
                    fma2(acc[i][0], a2, w.x);
                    fma2(acc[i][1], a2, w.y);
                }
            }
#pragma unroll
            for (int i = 0; i < 8; i++) {
                int e = e0 + tr * 8 + i;
                if (e < NE) {
                    float2 p0 = unpack2(acc[i][0]), p1 = unpack2(acc[i][1]);
                    float4 v = make_float4(silu(p0.x), silu(p0.y), silu(p1.x), silu(p1.y));
                    *(float4*)&g_x3[(size_t)e * 64 + tc * 4] = v;
                }
            }
        }
    } else {
        // ---- h = node_feats @ W_up ----
        const int n0 = (blockIdx.x - R123_BLKS) * 8;
        for (int i = t; i < 8 * CH; i += 128) {
            int n = n0 + i / CH;
            fs[i] = (n < NN) ? nf[(size_t)n * CH + (i & (CH - 1))] : 0.0f;
        }
        __syncthreads();
        float acc[8];
#pragma unroll
        for (int i = 0; i < 8; i++) acc[i] = 0.0f;
        for (int k = 0; k < CH; k++) {
            float wv = __ldg(&Wup[k * CH + t]);
#pragma unroll
            for (int i = 0; i < 8; i++) acc[i] += fs[i * CH + k] * wv;
        }
#pragma unroll
        for (int i = 0; i < 8; i++) {
            int n = n0 + i;
            if (n < NN) g_h[(size_t)n * CH + t] = acc[i];
        }
    }
}

// ---------------- layer 4 GEMM + gather, rank-ordered store (f32x2) ----------
// grid (8 col-chunks, edge tiles), 256 thr; thread = 8 rows x 4 cols.
// A tile duplicated (x,x) in dynamic smem -> k-loop is LDS.64 + 2 fma2.
static constexpr int R4_SMEM = 8192 * 8 + 128 * 8;  // A_dup 64KB + ssm/rsm

__global__ void __launch_bounds__(256, 3) k_r4(const float* __restrict__ W4) {
    extern __shared__ unsigned long long Ad[];      // [128 rows][64 k] dup pairs
    int* ssm = (int*)(Ad + 8192);                   // send per row
    int* rsm = ssm + 128;                           // rank per row
    const int t     = threadIdx.x;
    const int chunk = blockIdx.x;                   // 0..7 -> cols chunk*64..+63
    const int e0    = blockIdx.y * 128;

    for (int i = t; i < 8192; i += 256) {
        int e = e0 + (i >> 6);
        float v = (e < NE) ? g_x3[(size_t)e * 64 + (i & 63)] : 0.0f;
        ((float2*)Ad)[i] = make_float2(v, v);
    }
    if (t < 128) {
        int e = e0 + t;
        if (e < NE) {
            ssm[t] = g_send[e];
            rsm[t] = g_off[g_recv[e]] + g_ord[e];   // rank of edge in sorted order
        } else {
            ssm[t] = 0;
            rsm[t] = 0;
        }
    }
    __syncthreads();

    const int tr = t >> 4;   // rows tr*8..+7
    const int tc = t & 15;   // cols tc*4..+3 within chunk
    unsigned long long acc[8][2];
#pragma unroll
    for (int i = 0; i < 8; i++) { acc[i][0] = 0ULL; acc[i][1] = 0ULL; }

    const float* Wb = W4 + chunk * 64 + tc * 4;
#pragma unroll 4
    for (int k = 0; k < 64; k++) {
        ulonglong2 b = __ldg((const ulonglong2*)&Wb[(size_t)k * 512]);
#pragma unroll
        for (int i = 0; i < 8; i++) {
            unsigned long long a2 = Ad[(tr * 8 + i) * 64 + k];
            fma2(acc[i][0], a2, b.x);
            fma2(acc[i][1], a2, b.y);
        }
    }

    const int hcol = (chunk & 1) * 64 + tc * 4;     // h col = out col & 127
#pragma unroll
    for (int i = 0; i < 8; i++) {
        int row = tr * 8 + i;
        int e = e0 + row;
        if (e < NE) {
            float4 hv = __ldg((const float4*)&g_h[(size_t)ssm[row] * CH + hcol]);
            float2 a0 = unpack2(acc[i][0]), a1 = unpack2(acc[i][1]);
            *(float4*)&g_w[(size_t)rsm[row] * 512 + chunk * 64 + tc * 4] =
                make_float4(a0.x * hv.x, a0.y * hv.y, a1.x * hv.z, a1.y * hv.w);
        }
    }
}

// ---------------- scatter edge_attrs into rank order -------------------------
__global__ void k_scatter(const float* __restrict__ ea) {
    int e = blockIdx.x * 256 + threadIdx.x;
    if (e >= NE) return;
    int rk = g_off[g_recv[e]] + g_ord[e];
    const float4* src = (const float4*)&ea[(size_t)e * 16];
    float4* dst = (float4*)&g_sh[(size_t)rk * 16];
#pragma unroll
    for (int j = 0; j < 4; j++) dst[j] = src[j];
}

// ---------------- segmented aggregation: fully streaming ---------------------
__global__ void k_agg() {
    const int n = blockIdx.x;
    const int c = threadIdx.x;  // 128
    float acc[16];
#pragma unroll
    for (int m = 0; m < 16; m++) acc[m] = 0.0f;
    const int lo = g_off[n], hi = g_off[n + 1];

    int i = lo;
    for (; i + 2 <= hi; i += 2) {
        const float* wa = g_w + (size_t)i * 512;
        const float* wb = wa + 512;
        float a0 = wa[c], a1 = wa[128 + c], a2 = wa[256 + c], a3 = wa[384 + c];
        float b0 = wb[c], b1 = wb[128 + c], b2 = wb[256 + c], b3 = wb[384 + c];
        const float* sa = g_sh + (size_t)i * 16;
        const float* sb = sa + 16;
        acc[0] += __ldg(&sa[0]) * a0 + __ldg(&sb[0]) * b0;
#pragma unroll
        for (int m = 1; m < 4; m++) acc[m] += __ldg(&sa[m]) * a1 + __ldg(&sb[m]) * b1;
#pragma unroll
        for (int m = 4; m < 9; m++) acc[m] += __ldg(&sa[m]) * a2 + __ldg(&sb[m]) * b2;
#pragma unroll
        for (int m = 9; m < 16; m++) acc[m] += __ldg(&sa[m]) * a3 + __ldg(&sb[m]) * b3;
    }
    if (i < hi) {
        const float* wa = g_w + (size_t)i * 512;
        float a0 = wa[c], a1 = wa[128 + c], a2 = wa[256 + c], a3 = wa[384 + c];
        const float* sa = g_sh + (size_t)i * 16;
        acc[0] += __ldg(&sa[0]) * a0;
#pragma unroll
        for (int m = 1; m < 4; m++) acc[m] += __ldg(&sa[m]) * a1;
#pragma unroll
        for (int m = 4; m < 9; m++) acc[m] += __ldg(&sa[m]) * a2;
#pragma unroll
        for (int m = 9; m < 16; m++) acc[m] += __ldg(&sa[m]) * a3;
    }
    const float inv = 0.05f;  // 1/AVG_NUM_NEIGHBORS
#pragma unroll
    for (int m = 0; m < 16; m++)
        g_agg[(size_t)n * 2048 + m * 128 + c] = acc[m] * inv;
}

// ---------------- out transform per path (f32x2, staged coalesced stores) ----
template <int ML, int NB, int OFFM, int COLOFF>
__global__ void __launch_bounds__(256) k_out(const float* __restrict__ Wl,
                                             float* __restrict__ out) {
    constexpr int NR = ML * NB;  // <= 64
    __shared__ float As[64 * 129];
    const int t  = threadIdx.x;
    const int n0 = blockIdx.x * NB;
    for (int i = t; i < 64 * 128; i += 256) {
        int r = i >> 7, c = i & 127;
        float v = 0.0f;
        if (r < NR) {
            int n = n0 + r / ML;
            if (n < NN) v = g_agg[(size_t)n * 2048 + (OFFM + r % ML) * 128 + c];
        }
        As[r * 129 + c] = v;
    }
    __syncthreads();
    const int rg = t >> 5, lane = t & 31;
    unsigned long long acc[8][2];
#pragma unroll
    for (int i = 0; i < 8; i++) { acc[i][0] = 0ULL; acc[i][1] = 0ULL; }
    for (int c = 0; c < 128; c++) {
        ulonglong2 w = __ldg((const ulonglong2*)&Wl[c * 128 + lane * 4]);
#pragma unroll
        for (int i = 0; i < 8; i++) {
            unsigned long long a2 = bcast2(As[(rg * 8 + i) * 129 + c]);
            fma2(acc[i][0], a2, w.x);
            fma2(acc[i][1], a2, w.y);
        }
    }
    __syncthreads();   // all As reads done; reuse as output staging [r][d]
#pragma unroll
    for (int i = 0; i < 8; i++) {
        int r = rg * 8 + i;
        if (r < NR) {
            float2 p0 = unpack2(acc[i][0]), p1 = unpack2(acc[i][1]);
            float* d = &As[r * 129 + lane * 4];
            d[0] = p0.x; d[1] = p0.y; d[2] = p1.x; d[3] = p1.y;
        }
    }
    __syncthreads();
    // linear, fully coalesced store: within node, offset rem = d*ML + m
    for (int idx = t; idx < NB * ML * 128; idx += 256) {
        int n_l = idx / (ML * 128);
        int rem = idx - n_l * (ML * 128);
        int d = rem / ML;
        int m = rem - d * ML;
        int n = n0 + n_l;
        if (n < NN)
            out[(size_t)n * OUTW + COLOFF + rem] = As[(n_l * ML + m) * 129 + d];
    }
}

// ---------------- one-body term ----------------------------------------------
__global__ void k_ob(const float* __restrict__ pf, const float* __restrict__ nf,
                     const float* __restrict__ lc, const float* __restrict__ Wp,
                     const float* __restrict__ Wn, const float* __restrict__ Wc,
                     float* __restrict__ out) {
    __shared__ float pfs[16 * 16];
    __shared__ float nfs[16 * 128];
    __shared__ float lcs[16];
    const int t  = threadIdx.x;
    const int n0 = blockIdx.x * 16;
    for (int i = t; i < 16 * 16; i += 128) {
        int n = n0 + i / 16;
        pfs[i] = (n < NN) ? pf[(size_t)n * 16 + (i & 15)] * 0.1f : 0.0f;
    }
    for (int i = t; i < 16 * 128; i += 128) {
        int n = n0 + i / 128;
        nfs[i] = (n < NN) ? nf[(size_t)n * 128 + (i & 127)] : 0.0f;
    }
    if (t < 16) {
        int n = n0 + t;
        lcs[t] = (n < NN) ? lc[n] : 0.0f;
    }
    __syncthreads();
    float acc[16];
    float wc = __ldg(&Wc[t]);
#pragma unroll
    for (int i = 0; i < 16; i++) acc[i] = lcs[i] * wc;
    for (int k = 0; k < 16; k++) {
        float wv = __ldg(&Wp[k * 128 + t]);
#pragma unroll
        for (int i = 0; i < 16; i++) acc[i] += pfs[i * 16 + k] * wv;
    }
    for (int k = 0; k < 128; k++) {
        float wv = __ldg(&Wn[k * 128 + t]);
#pragma unroll
        for (int i = 0; i < 16; i++) acc[i] += nfs[i * 128 + k] * wv;
    }
#pragma unroll
    for (int i = 0; i < 16; i++) {
        int n = n0 + i;
        if (n < NN) out[(size_t)n * OUTW + t] += acc[i];
    }
}

// ---------------- launch -----------------------------------------------------
extern "C" void kernel_launch(void* const* d_in, const int* in_sizes, int n_in,
                              void* d_out, int out_size) {
    const float* node_feats = (const float*)d_in[1];
    const float* edge_attrs = (const float*)d_in[2];
    const float* edge_feats = (const float*)d_in[3];
    const int*   edge_index = (const int*)d_in[4];
    const float* potential  = (const float*)d_in[5];
    const float* charges    = (const float*)d_in[6];
    const float* W_up = (const float*)d_in[7];
    const float* W1   = (const float*)d_in[8];
    const float* W2   = (const float*)d_in[9];
    const float* W3   = (const float*)d_in[10];
    const float* W4   = (const float*)d_in[11];
    const float* Wout = (const float*)d_in[12];
    const float* Wp   = (const float*)d_in[13];
    const float* Wn   = (const float*)d_in[14];
    const float* Wc   = (const float*)d_in[15];
    float*       out  = (float*)d_out;

    cudaFuncSetAttribute(k_r4, cudaFuncAttributeMaxDynamicSharedMemorySize, R4_SMEM);

    k_convert<<<(NE + 255) / 256, 256>>>(edge_index);                  // 0
    k_scan<<<1, 1024>>>();                                             // 1
    k_pre<<<R123_BLKS + H_BLKS, 128>>>(edge_feats, W1, W2, W3,         // 2
                                       node_feats, W_up);
    k_r4<<<dim3(8, (NE + 127) / 128), 256, R4_SMEM>>>(W4);             // 3 <- profiled
    k_scatter<<<(NE + 255) / 256, 256>>>(edge_attrs);                  // 4
    k_agg<<<NN, 128>>>();                                              // 5

    k_out<1, 64, 0, 0><<<(NN + 63) / 64, 256>>>(Wout, out);
    k_out<3, 21, 1, 128><<<(NN + 20) / 21, 256>>>(Wout + 1 * CH * CH, out);
    k_out<5, 12, 4, 512><<<(NN + 11) / 12, 256>>>(Wout + 2 * CH * CH, out);
    k_out<7, 9, 9, 1152><<<(NN + 8) / 9, 256>>>(Wout + 3 * CH * CH, out);

    k_ob<<<(NN + 15) / 16, 128>>>(potential, node_feats, charges, Wp, Wn, Wc, out);
}

// round 7
// speedup vs baseline: 1.5170x; 1.1131x over previous
#include <cuda_runtime.h>
#include <cuda_bf16.h>

static constexpr int NN   = 25000;
static constexpr int NE   = 500000;
static constexpr int CH   = 128;
static constexpr int OUTW = 2048;

// ---------------- scratch (static device globals; no allocation allowed) ----
__device__ float g_h[NN * CH];                   // 12.8 MB
__device__ float g_x3[(size_t)NE * 64];          // 128 MB
__device__ float g_w[(size_t)NE * 512];          // 1.024 GB (rank-ordered rows)
__device__ float g_sh[(size_t)NE * 16];          // 32 MB  (rank-ordered edge_attrs)
__device__ float g_agg[(size_t)NN * 2048];       // 204.8 MB
__device__ uint4 g_Bf[8192];                     // W4 bf16-split mma B-fragments (128 KB)
__device__ int   g_cnt[NN];                      // zero-init; scan re-zeroes
__device__ int   g_off[NN + 1];
__device__ int   g_ord[NE];                      // per-receiver ordinal
__device__ int   g_send[NE];
__device__ int   g_recv[NE];

__device__ __forceinline__ float silu(float x) {
    return __fdividef(x, 1.0f + __expf(-x));
}

// packed f32x2 helpers (Blackwell; PTX-only)
__device__ __forceinline__ unsigned long long bcast2(float a) {
    unsigned long long r;
    asm("mov.b64 %0, {%1, %1};" : "=l"(r) : "f"(a));
    return r;
}
__device__ __forceinline__ void fma2(unsigned long long& acc, unsigned long long a,
                                     unsigned long long b) {
    asm("fma.rn.f32x2 %0, %1, %2, %0;" : "+l"(acc) : "l"(a), "l"(b));
}
__device__ __forceinline__ float2 unpack2(unsigned long long v) {
    float lo, hi;
    asm("mov.b64 {%0, %1}, %2;" : "=f"(lo), "=f"(hi) : "l"(v));
    return make_float2(lo, hi);
}

// ---------------- mma helpers (legacy HMMA path, sm_80+; works on sm_100) ----
__device__ __forceinline__ unsigned smem_u32(const void* p) {
    unsigned a;
    asm("{ .reg .u64 t; cvta.to.shared.u64 t, %1; cvt.u32.u64 %0, t; }"
        : "=r"(a) : "l"(p));
    return a;
}
__device__ __forceinline__ void ldmatrix_x4(unsigned* r, unsigned addr) {
    asm volatile("ldmatrix.sync.aligned.m8n8.x4.shared.b16 {%0,%1,%2,%3}, [%4];"
                 : "=r"(r[0]), "=r"(r[1]), "=r"(r[2]), "=r"(r[3]) : "r"(addr));
}
__device__ __forceinline__ void mma_bf16(float* d, const unsigned* a,
                                         unsigned b0, unsigned b1) {
    asm volatile(
        "mma.sync.aligned.m16n8k16.row.col.f32.bf16.bf16.f32 "
        "{%0,%1,%2,%3}, {%4,%5,%6,%7}, {%8,%9}, {%0,%1,%2,%3};"
        : "+f"(d[0]), "+f"(d[1]), "+f"(d[2]), "+f"(d[3])
        : "r"(a[0]), "r"(a[1]), "r"(a[2]), "r"(a[3]), "r"(b0), "r"(b1));
}
__device__ __forceinline__ unsigned pack_bf2(float x, float y) {
    __nv_bfloat162 q = __floats2bfloat162_rn(x, y);
    return *(unsigned*)&q;
}

// ---------------- convert: dtype detect + int32 + fused hist/ordinal ---------
__global__ void k_convert(const int* __restrict__ ei) {
    int e = blockIdx.x * 256 + threadIdx.x;
    if (e >= NE) return;
    bool is64 = true;
#pragma unroll
    for (int i = 0; i < 8; i++) is64 &= (__ldg(&ei[2 * i + 1]) == 0);
    int s, r;
    if (is64) {
        const long long* p = (const long long*)ei;
        s = (int)p[e];
        r = (int)p[NE + e];
    } else {
        s = ei[e];
        r = ei[NE + e];
    }
    s = min(max(s, 0), NN - 1);
    r = min(max(r, 0), NN - 1);
    g_send[e] = s;
    g_recv[e] = r;
    g_ord[e] = atomicAdd(&g_cnt[r], 1);
}

// ---------------- scan (exclusive prefix over g_cnt; re-zeroes g_cnt) --------
__global__ void k_scan() {
    __shared__ int s[1024];
    const int t = threadIdx.x;
    const int CK = 25;
    const int base = t * CK;
    int loc[CK];
    int sum = 0;
#pragma unroll
    for (int i = 0; i < CK; i++) {
        int idx = base + i;
        int c = (idx < NN) ? g_cnt[idx] : 0;
        if (idx < NN) g_cnt[idx] = 0;
        loc[i] = sum;
        sum += c;
    }
    s[t] = sum;
    __syncthreads();
    for (int d = 1; d < 1024; d <<= 1) {
        int v = (t >= d) ? s[t - d] : 0;
        __syncthreads();
        s[t] += v;
        __syncthreads();
    }
    int pre = (t == 0) ? 0 : s[t - 1];
#pragma unroll
    for (int i = 0; i < CK; i++) {
        int idx = base + i;
        if (idx < NN) g_off[idx] = pre + loc[i];
    }
    if (t == 1023) g_off[NN] = s[1023];
}

// ---------------- k_pre: r123 (f32x2) + h GEMM + W4 B-fragment prep ----------
static constexpr int R123_BLKS = (NE + 63) / 64;   // 7813
static constexpr int H_BLKS    = (NN + 7) / 8;     // 3125
static constexpr int BF_BLKS   = 64;               // 8192 fragments / 128 thr

__global__ void __launch_bounds__(128) k_pre(
    const float* __restrict__ ef, const float* __restrict__ W1,
    const float* __restrict__ W2, const float* __restrict__ W3,
    const float* __restrict__ nf, const float* __restrict__ Wup,
    const float* __restrict__ W4) {
    __shared__ float efs[64 * 8];
    __shared__ float bufA[64 * 64];
    __shared__ float bufB[64 * 64];
    __shared__ float fs[8 * CH];
    const int t = threadIdx.x;

    if (blockIdx.x < R123_BLKS) {
        const int e0 = blockIdx.x * 64;
        for (int i = t; i < 64 * 8; i += 128) {
            int e = e0 + i / 8;
            efs[i] = (e < NE) ? ef[(size_t)e * 8 + (i & 7)] : 0.0f;
        }
        __syncthreads();
        const int tr = t >> 4;
        const int tc = t & 15;
        {
            unsigned long long acc[8][2];
#pragma unroll
            for (int i = 0; i < 8; i++) { acc[i][0] = 0ULL; acc[i][1] = 0ULL; }
#pragma unroll
            for (int k = 0; k < 8; k++) {
                ulonglong2 w = __ldg((const ulonglong2*)&W1[k * 64 + tc * 4]);
#pragma unroll
                for (int i = 0; i < 8; i++) {
                    unsigned long long a2 = bcast2(efs[(tr * 8 + i) * 8 + k]);
                    fma2(acc[i][0], a2, w.x);
                    fma2(acc[i][1], a2, w.y);
                }
            }
#pragma unroll
            for (int i = 0; i < 8; i++) {
                float2 p0 = unpack2(acc[i][0]), p1 = unpack2(acc[i][1]);
                float* d = &bufA[(tr * 8 + i) * 64 + tc * 4];
                d[0] = silu(p0.x); d[1] = silu(p0.y);
                d[2] = silu(p1.x); d[3] = silu(p1.y);
            }
        }
        __syncthreads();
        {
            unsigned long long acc[8][2];
#pragma unroll
            for (int i = 0; i < 8; i++) { acc[i][0] = 0ULL; acc[i][1] = 0ULL; }
            for (int k = 0; k < 64; k++) {
                ulonglong2 w = __ldg((const ulonglong2*)&W2[k * 64 + tc * 4]);
#pragma unroll
                for (int i = 0; i < 8; i++) {
                    unsigned long long a2 = bcast2(bufA[(tr * 8 + i) * 64 + k]);
                    fma2(acc[i][0], a2, w.x);
                    fma2(acc[i][1], a2, w.y);
                }
            }
            __syncthreads();
#pragma unroll
            for (int i = 0; i < 8; i++) {
                float2 p0 = unpack2(acc[i][0]), p1 = unpack2(acc[i][1]);
                float* d = &bufB[(tr * 8 + i) * 64 + tc * 4];
                d[0] = silu(p0.x); d[1] = silu(p0.y);
                d[2] = silu(p1.x); d[3] = silu(p1.y);
            }
        }
        __syncthreads();
        {
            unsigned long long acc[8][2];
#pragma unroll
            for (int i = 0; i < 8; i++) { acc[i][0] = 0ULL; acc[i][1] = 0ULL; }
            for (int k = 0; k < 64; k++) {
                ulonglong2 w = __ldg((const ulonglong2*)&W3[k * 64 + tc * 4]);
#pragma unroll
                for (int i = 0; i < 8; i++) {
                    unsigned long long a2 = bcast2(bufB[(tr * 8 + i) * 64 + k]);
                    fma2(acc[i][0], a2, w.x);
                    fma2(acc[i][1], a2, w.y);
                }
            }
#pragma unroll
            for (int i = 0; i < 8; i++) {
                int e = e0 + tr * 8 + i;
                if (e < NE) {
                    float2 p0 = unpack2(acc[i][0]), p1 = unpack2(acc[i][1]);
                    float4 v = make_float4(silu(p0.x), silu(p0.y), silu(p1.x), silu(p1.y));
                    *(float4*)&g_x3[(size_t)e * 64 + tc * 4] = v;
                }
            }
        }
    } else if (blockIdx.x < R123_BLKS + H_BLKS) {
        // ---- h = node_feats @ W_up ----
        const int n0 = (blockIdx.x - R123_BLKS) * 8;
        for (int i = t; i < 8 * CH; i += 128) {
            int n = n0 + i / CH;
            fs[i] = (n < NN) ? nf[(size_t)n * CH + (i & (CH - 1))] : 0.0f;
        }
        __syncthreads();
        float acc[8];
#pragma unroll
        for (int i = 0; i < 8; i++) acc[i] = 0.0f;
        for (int k = 0; k < CH; k++) {
            float wv = __ldg(&Wup[k * CH + t]);
#pragma unroll
            for (int i = 0; i < 8; i++) acc[i] += fs[i * CH + k] * wv;
        }
#pragma unroll
        for (int i = 0; i < 8; i++) {
            int n = n0 + i;
            if (n < NN) g_h[(size_t)n * CH + t] = acc[i];
        }
    } else {
        // ---- W4 -> bf16-split mma B-fragments, fragment-order packed ----
        // idx = chunk*1024 + (ks*8+nt)*32 + lane
        int idx = (blockIdx.x - R123_BLKS - H_BLKS) * 128 + t;
        if (idx < 8192) {
            int chunk = idx >> 10;
            int w     = idx & 1023;
            int ksnt  = w >> 5;         // ks*8 + nt
            int lane  = w & 31;
            int ks = ksnt >> 3, nt = ksnt & 7;
            int n  = chunk * 64 + nt * 8 + (lane >> 2);
            int k0 = ks * 16 + (lane & 3) * 2;
            float v00 = __ldg(&W4[(size_t)k0 * 512 + n]);
            float v01 = __ldg(&W4[(size_t)(k0 + 1) * 512 + n]);
            float v08 = __ldg(&W4[(size_t)(k0 + 8) * 512 + n]);
            float v09 = __ldg(&W4[(size_t)(k0 + 9) * 512 + n]);
            float h00 = __bfloat162float(__float2bfloat16_rn(v00));
            float h01 = __bfloat162float(__float2bfloat16_rn(v01));
            float h08 = __bfloat162float(__float2bfloat16_rn(v08));
            float h09 = __bfloat162float(__float2bfloat16_rn(v09));
            uint4 r;
            r.x = pack_bf2(h00, h01);
            r.y = pack_bf2(h08, h09);
            r.z = pack_bf2(v00 - h00, v01 - h01);
            r.w = pack_bf2(v08 - h08, v09 - h09);
            g_Bf[idx] = r;
        }
    }
}

// ---------------- layer 4: HMMA bf16-split GEMM + gather, rank-ordered store -
// Block: M=128 edges x N=64 cols (chunk) x K=64.  Warp w -> rows w*16..+15.
// D = A0*B0 + A0*B1 + A1*B0 (fp32 accum); w = D * h[send], row = rank.
static constexpr int APAD = 72;  // bf16 elems/row; 144B stride avoids bank camping

__global__ void __launch_bounds__(256) k_r4() {
    __shared__ __align__(16) __nv_bfloat16 A0s[128 * APAD];
    __shared__ __align__(16) __nv_bfloat16 A1s[128 * APAD];
    __shared__ int ssm[128];
    __shared__ int rsm[128];
    const int t     = threadIdx.x;
    const int chunk = blockIdx.x;          // 0..7 -> cols chunk*64..+63
    const int e0    = blockIdx.y * 128;

    // ---- A tile: fp32 -> bf16 hi/lo split ----
    for (int i = t; i < 2048; i += 256) {  // float4 granules: 128 rows x 16
        int row = i >> 4, k4 = (i & 15) << 2;
        int e = e0 + row;
        float4 v = (e < NE) ? *(const float4*)&g_x3[(size_t)e * 64 + k4]
                            : make_float4(0.f, 0.f, 0.f, 0.f);
        float hx = __bfloat162float(__float2bfloat16_rn(v.x));
        float hy = __bfloat162float(__float2bfloat16_rn(v.y));
        float hz = __bfloat162float(__float2bfloat16_rn(v.z));
        float hw = __bfloat162float(__float2bfloat16_rn(v.w));
        unsigned* a0p = (unsigned*)&A0s[row * APAD + k4];
        unsigned* a1p = (unsigned*)&A1s[row * APAD + k4];
        a0p[0] = pack_bf2(hx, hy);
        a0p[1] = pack_bf2(hz, hw);
        a1p[0] = pack_bf2(v.x - hx, v.y - hy);
        a1p[1] = pack_bf2(v.z - hz, v.w - hw);
    }
    if (t < 128) {
        int e = e0 + t;
        if (e < NE) {
            ssm[t] = g_send[e];
            rsm[t] = g_off[g_recv[e]] + g_ord[e];
        } else {
            ssm[t] = 0;
            rsm[t] = 0;
        }
    }
    __syncthreads();

    const int lane = t & 31, wid = t >> 5;
    const int mrow0 = wid * 16;
    // ldmatrix.x4 row addresses: t<16 -> row t @k0; t>=16 -> row t-16 @k0+8
    const int arow = mrow0 + (lane & 15);
    const int acol = (lane >> 4) << 3;
    unsigned a0base = smem_u32(&A0s[arow * APAD + acol]);
    unsigned a1base = smem_u32(&A1s[arow * APAD + acol]);

    float acc[8][4];
#pragma unroll
    for (int i = 0; i < 8; i++)
#pragma unroll
        for (int j = 0; j < 4; j++) acc[i][j] = 0.0f;

    const uint4* Bp = g_Bf + chunk * 1024 + lane;
#pragma unroll
    for (int ks = 0; ks < 4; ks++) {
        unsigned a0[4], a1[4];
        ldmatrix_x4(a0, a0base + ks * 32);   // 16 bf16 k-cols = 32 bytes
        ldmatrix_x4(a1, a1base + ks * 32);
#pragma unroll
        for (int nt = 0; nt < 8; nt++) {
            uint4 b = __ldg(&Bp[(ks * 8 + nt) * 32]);
            mma_bf16(acc[nt], a0, b.x, b.y);   // A0*B0
            mma_bf16(acc[nt], a0, b.z, b.w);   // A0*B1
            mma_bf16(acc[nt], a1, b.x, b.y);   // A1*B0
        }
    }

    // ---- epilogue: x h[send], store at rank row ----
    const int r    = lane >> 2;
    const int row0 = mrow0 + r, row1 = row0 + 8;
    const int cp   = (lane & 3) << 1;
    const bool v0 = (e0 + row0) < NE, v1 = (e0 + row1) < NE;
    const int s0 = ssm[row0], s1 = ssm[row1];
    const size_t w0 = (size_t)rsm[row0] * 512, w1 = (size_t)rsm[row1] * 512;
#pragma unroll
    for (int nt = 0; nt < 8; nt++) {
        int colbase = chunk * 64 + nt * 8 + cp;
        int hcol = colbase & 127;
        if (v0) {
            float2 hv = *(const float2*)&g_h[(size_t)s0 * CH + hcol];
            *(float2*)&g_w[w0 + colbase] =
                make_float2(acc[nt][0] * hv.x, acc[nt][1] * hv.y);
        }
        if (v1) {
            float2 hv = *(const float2*)&g_h[(size_t)s1 * CH + hcol];
            *(float2*)&g_w[w1 + colbase] =
                make_float2(acc[nt][2] * hv.x, acc[nt][3] * hv.y);
        }
    }
}

// ---------------- scatter edge_attrs into rank order -------------------------
__global__ void k_scatter(const float* __restrict__ ea) {
    int e = blockIdx.x * 256 + threadIdx.x;
    if (e >= NE) return;
    int rk = g_off[g_recv[e]] + g_ord[e];
    const float4* src = (const float4*)&ea[(size_t)e * 16];
    float4* dst = (float4*)&g_sh[(size_t)rk * 16];
#pragma unroll
    for (int j = 0; j < 4; j++) dst[j] = src[j];
}

// ---------------- segmented aggregation: fully streaming ---------------------
__global__ void k_agg() {
    const int n = blockIdx.x;
    const int c = threadIdx.x;
    float acc[16];
#pragma unroll
    for (int m = 0; m < 16; m++) acc[m] = 0.0f;
    const int lo = g_off[n], hi = g_off[n + 1];

    int i = lo;
    for (; i + 2 <= hi; i += 2) {
        const float* wa = g_w + (size_t)i * 512;
        const float* wb = wa + 512;
        float a0 = wa[c], a1 = wa[128 + c], a2 = wa[256 + c], a3 = wa[384 + c];
        float b0 = wb[c], b1 = wb[128 + c], b2 = wb[256 + c], b3 = wb[384 + c];
        const float* sa = g_sh + (size_t)i * 16;
        const float* sb = sa + 16;
        acc[0] += __ldg(&sa[0]) * a0 + __ldg(&sb[0]) * b0;
#pragma unroll
        for (int m = 1; m < 4; m++) acc[m] += __ldg(&sa[m]) * a1 + __ldg(&sb[m]) * b1;
#pragma unroll
        for (int m = 4; m < 9; m++) acc[m] += __ldg(&sa[m]) * a2 + __ldg(&sb[m]) * b2;
#pragma unroll
        for (int m = 9; m < 16; m++) acc[m] += __ldg(&sa[m]) * a3 + __ldg(&sb[m]) * b3;
    }
    if (i < hi) {
        const float* wa = g_w + (size_t)i * 512;
        float a0 = wa[c], a1 = wa[128 + c], a2 = wa[256 + c], a3 = wa[384 + c];
        const float* sa = g_sh + (size_t)i * 16;
        acc[0] += __ldg(&sa[0]) * a0;
#pragma unroll
        for (int m = 1; m < 4; m++) acc[m] += __ldg(&sa[m]) * a1;
#pragma unroll
        for (int m = 4; m < 9; m++) acc[m] += __ldg(&sa[m]) * a2;
#pragma unroll
        for (int m = 9; m < 16; m++) acc[m] += __ldg(&sa[m]) * a3;
    }
    const float inv = 0.05f;
#pragma unroll
    for (int m = 0; m < 16; m++)
        g_agg[(size_t)n * 2048 + m * 128 + c] = acc[m] * inv;
}

// ---------------- out transform per path (f32x2, staged coalesced stores) ----
template <int ML, int NB, int OFFM, int COLOFF>
__global__ void __launch_bounds__(256) k_out(const float* __restrict__ Wl,
                                             float* __restrict__ out) {
    constexpr int NR = ML * NB;
    __shared__ float As[64 * 129];
    const int t  = threadIdx.x;
    const int n0 = blockIdx.x * NB;
    for (int i = t; i < 64 * 128; i += 256) {
        int r = i >> 7, c = i & 127;
        float v = 0.0f;
        if (r < NR) {
            int n = n0 + r / ML;
            if (n < NN) v = g_agg[(size_t)n * 2048 + (OFFM + r % ML) * 128 + c];
        }
        As[r * 129 + c] = v;
    }
    __syncthreads();
    const int rg = t >> 5, lane = t & 31;
    unsigned long long acc[8][2];
#pragma unroll
    for (int i = 0; i < 8; i++) { acc[i][0] = 0ULL; acc[i][1] = 0ULL; }
    for (int c = 0; c < 128; c++) {
        ulonglong2 w = __ldg((const ulonglong2*)&Wl[c * 128 + lane * 4]);
#pragma unroll
        for (int i = 0; i < 8; i++) {
            unsigned long long a2 = bcast2(As[(rg * 8 + i) * 129 + c]);
            fma2(acc[i][0], a2, w.x);
            fma2(acc[i][1], a2, w.y);
        }
    }
    __syncthreads();
#pragma unroll
    for (int i = 0; i < 8; i++) {
        int r = rg * 8 + i;
        if (r < NR) {
            float2 p0 = unpack2(acc[i][0]), p1 = unpack2(acc[i][1]);
            float* d = &As[r * 129 + lane * 4];
            d[0] = p0.x; d[1] = p0.y; d[2] = p1.x; d[3] = p1.y;
        }
    }
    __syncthreads();
    for (int idx = t; idx < NB * ML * 128; idx += 256) {
        int n_l = idx / (ML * 128);
        int rem = idx - n_l * (ML * 128);
        int d = rem / ML;
        int m = rem - d * ML;
        int n = n0 + n_l;
        if (n < NN)
            out[(size_t)n * OUTW + COLOFF + rem] = As[(n_l * ML + m) * 129 + d];
    }
}

// ---------------- one-body term ----------------------------------------------
__global__ void k_ob(const float* __restrict__ pf, const float* __restrict__ nf,
                     const float* __restrict__ lc, const float* __restrict__ Wp,
                     const float* __restrict__ Wn, const float* __restrict__ Wc,
                     float* __restrict__ out) {
    __shared__ float pfs[16 * 16];
    __shared__ float nfs[16 * 128];
    __shared__ float lcs[16];
    const int t  = threadIdx.x;
    const int n0 = blockIdx.x * 16;
    for (int i = t; i < 16 * 16; i += 128) {
        int n = n0 + i / 16;
        pfs[i] = (n < NN) ? pf[(size_t)n * 16 + (i & 15)] * 0.1f : 0.0f;
    }
    for (int i = t; i < 16 * 128; i += 128) {
        int n = n0 + i / 128;
        nfs[i] = (n < NN) ? nf[(size_t)n * 128 + (i & 127)] : 0.0f;
    }
    if (t < 16) {
        int n = n0 + t;
        lcs[t] = (n < NN) ? lc[n] : 0.0f;
    }
    __syncthreads();
    float acc[16];
    float wc = __ldg(&Wc[t]);
#pragma unroll
    for (int i = 0; i < 16; i++) acc[i] = lcs[i] * wc;
    for (int k = 0; k < 16; k++) {
        float wv = __ldg(&Wp[k * 128 + t]);
#pragma unroll
        for (int i = 0; i < 16; i++) acc[i] += pfs[i * 16 + k] * wv;
    }
    for (int k = 0; k < 128; k++) {
        float wv = __ldg(&Wn[k * 128 + t]);
#pragma unroll
        for (int i = 0; i < 16; i++) acc[i] += nfs[i * 128 + k] * wv;
    }
#pragma unroll
    for (int i = 0; i < 16; i++) {
        int n = n0 + i;
        if (n < NN) out[(size_t)n * OUTW + t] += acc[i];
    }
}

// ---------------- launch -----------------------------------------------------
extern "C" void kernel_launch(void* const* d_in, const int* in_sizes, int n_in,
                              void* d_out, int out_size) {
    const float* node_feats = (const float*)d_in[1];
    const float* edge_attrs = (const float*)d_in[2];
    const float* edge_feats = (const float*)d_in[3];
    const int*   edge_index = (const int*)d_in[4];
    const float* potential  = (const float*)d_in[5];
    const float* charges    = (const float*)d_in[6];
    const float* W_up = (const float*)d_in[7];
    const float* W1   = (const float*)d_in[8];
    const float* W2   = (const float*)d_in[9];
    const float* W3   = (const float*)d_in[10];
    const float* W4   = (const float*)d_in[11];
    const float* Wout = (const float*)d_in[12];
    const float* Wp   = (const float*)d_in[13];
    const float* Wn   = (const float*)d_in[14];
    const float* Wc   = (const float*)d_in[15];
    float*       out  = (float*)d_out;

    k_convert<<<(NE + 255) / 256, 256>>>(edge_index);                  // 0
    k_scan<<<1, 1024>>>();                                             // 1
    k_pre<<<R123_BLKS + H_BLKS + BF_BLKS, 128>>>(edge_feats, W1, W2,   // 2
                                                 W3, node_feats, W_up, W4);
    k_r4<<<dim3(8, (NE + 127) / 128), 256>>>();                        // 3 <- profiled
    k_scatter<<<(NE + 255) / 256, 256>>>(edge_attrs);                  // 4
    k_agg<<<NN, 128>>>();                                              // 5

    k_out<1, 64, 0, 0><<<(NN + 63) / 64, 256>>>(Wout, out);
    k_out<3, 21, 1, 128><<<(NN + 20) / 21, 256>>>(Wout + 1 * CH * CH, out);
    k_out<5, 12, 4, 512><<<(NN + 11) / 12, 256>>>(Wout + 2 * CH * CH, out);
    k_out<7, 9, 9, 1152><<<(NN + 8) / 9, 256>>>(Wout + 3 * CH * CH, out);

    k_ob<<<(NN + 15) / 16, 128>>>(potential, node_feats, charges, Wp, Wn, Wc, out);
}